// round 1
// baseline (speedup 1.0000x reference)
#include <cuda_runtime.h>
#include <math.h>

#define NNODES 16384

// ---------------- scratch (static device globals; no allocation) ----------------
__device__ float d_sc[(long)NNODES * 384];    // [s, s^2, |v|^2/sqrt3]
__device__ float d_h [(long)NNODES * 384];    // silu(sc @ w1 / sqrt384)
__device__ float d_g [(long)NNODES * 640];    // h @ w2[:, :640] / sqrt384
__device__ float d_s [(long)NNODES * 128];    // scalar state
__device__ float d_v [(long)NNODES * 384];    // vector state (N, C, 3)
__device__ float d_vt[3L * NNODES * 256];     // gated vec, transposed per d: (3, N, 256)

// ---------------- prep: build sc = [s, s*s, |v|^2/sqrt3]; optionally copy state --
__global__ void prep_kernel(const float* __restrict__ S, int ldS,
                            const float* __restrict__ V, int ldV,
                            float* __restrict__ sc,
                            float* __restrict__ sbuf, float* __restrict__ vbuf,
                            int copy)
{
    int idx = blockIdx.x * blockDim.x + threadIdx.x;
    if (idx >= NNODES * 128) return;
    int n = idx >> 7, c = idx & 127;
    float s = S[(long)n * ldS + c];
    const float* vp = V + (long)n * ldV + 3 * c;
    float vx = vp[0], vy = vp[1], vz = vp[2];
    float* scp = sc + (long)n * 384 + c;
    scp[0]   = s;
    scp[128] = s * s;
    scp[256] = (vx * vx + vy * vy + vz * vz) * 0.57735026918962576451f; // 1/sqrt(3)
    if (copy) {
        sbuf[(long)n * 128 + c] = s;
        float* vb = vbuf + (long)n * 384 + 3 * c;
        vb[0] = vx; vb[1] = vy; vb[2] = vz;
    }
}

// ---------------- gatevec: vecT[d][n][m] = gated vec component --------------------
__global__ void gatevec_kernel(const float* __restrict__ sc,
                               const float* __restrict__ vbuf,
                               const float* __restrict__ g,
                               float* __restrict__ vecT)
{
    int idx = blockIdx.x * blockDim.x + threadIdx.x;
    if (idx >= NNODES * 128) return;
    int n = idx >> 7, m = idx & 127;
    float s  = sc[(long)n * 384 + m];              // original s lives in sc[:, :128]
    const float* vp = vbuf + (long)n * 384 + 3 * m;
    float gv1 = g[(long)n * 640 + 384 + m];        // gate for v part
    float gv2 = g[(long)n * 640 + 512 + m];        // gate for sv part
    float c2  = 1.41421356237309514547f * s * gv2; // sqrt2 * s * gate
    #pragma unroll
    for (int d = 0; d < 3; d++) {
        float vd = vp[d];
        vecT[(long)d * NNODES * 256 + (long)n * 256 + m]       = vd * gv1;
        vecT[(long)d * NNODES * 256 + (long)n * 256 + 128 + m] = vd * c2;
    }
}

// ---------------- equivariant layernorm (one block of 128 threads per node) -------
__device__ __forceinline__ float blk_red(float val, float* sh, int t)
{
    #pragma unroll
    for (int o = 16; o; o >>= 1) val += __shfl_xor_sync(0xffffffffu, val, o);
    if ((t & 31) == 0) sh[t >> 5] = val;
    __syncthreads();
    val = sh[0] + sh[1] + sh[2] + sh[3];
    __syncthreads();
    return val;
}

__global__ void ln_kernel(float* __restrict__ s, float* __restrict__ v,
                          const float* __restrict__ g0, const float* __restrict__ g1)
{
    __shared__ float sh[4];
    int n = blockIdx.x, t = threadIdx.x;
    float sv = s[(long)n * 128 + t];
    float mu = blk_red(sv, sh, t) * (1.0f / 128.0f);
    float dd = sv - mu;
    float var = blk_red(dd * dd, sh, t) * (1.0f / 128.0f);
    float sd = sqrtf(var + 1e-6f);
    float* vp = v + (long)n * 384 + 3 * t;
    float vx = vp[0], vy = vp[1], vz = vp[2];
    float msq = blk_red(vx * vx + vy * vy + vz * vz, sh, t) * (1.0f / 384.0f);
    float rms = sqrtf(msq + 1e-6f);
    s[(long)n * 128 + t] = dd / sd * g0[t];
    float scl = g1[t] / rms;
    vp[0] = vx * scl; vp[1] = vy * scl; vp[2] = vz * scl;
}

// ---------------- SGEMM: 128x128x32 tiles, 256 threads, 8x8 per thread ------------
// C[row*ldc_row + col*ldc_col + c_off] = epi(acc*scale [+ R[row*ldr_row+col*ldr_col+r_off]])
// EPI: 0 = silu, 1 = plain, 2 = residual add.  GATED: A element-wise multiplied by A2.
template<int EPI, bool GATED>
__global__ void __launch_bounds__(256)
gemm_kernel(const float* __restrict__ A, int lda,
            const float* __restrict__ A2, int lda2,
            const float* __restrict__ B, int ldb,
            float* __restrict__ C, int ldc_row, int ldc_col, int c_off,
            const float* __restrict__ R, int ldr_row, int ldr_col, int r_off,
            int K, float scale)
{
    __shared__ float As[32][132];   // transposed, +4 pad to kill store conflicts
    __shared__ float Bs[32][128];

    const int t = threadIdx.x;
    const int crow0 = blockIdx.y * 128;
    const int ccol0 = blockIdx.x * 128;
    A += (long)crow0 * lda;
    if (GATED) A2 += (long)crow0 * lda2;
    B += ccol0;

    const int arow = t >> 3, acol = (t & 7) * 4;   // A: 128 rows x 8 float4/row
    const int brow = t >> 5, bcol = (t & 31) * 4;  // B: 32 rows x 32 float4/row
    const int ty = t >> 4, tx = t & 15;

    float acc[8][8];
    #pragma unroll
    for (int i = 0; i < 8; i++)
        #pragma unroll
        for (int j = 0; j < 8; j++) acc[i][j] = 0.0f;

    for (int kt = 0; kt < K; kt += 32) {
        float4 av[4], bv[4];
        #pragma unroll
        for (int i = 0; i < 4; i++) {
            int r = arow + i * 32;
            av[i] = *(const float4*)(A + (long)r * lda + kt + acol);
            if (GATED) {
                float4 gq = *(const float4*)(A2 + (long)r * lda2 + kt + acol);
                av[i].x *= gq.x; av[i].y *= gq.y; av[i].z *= gq.z; av[i].w *= gq.w;
            }
        }
        #pragma unroll
        for (int i = 0; i < 4; i++) {
            int r = brow + i * 8;
            bv[i] = *(const float4*)(B + (long)(kt + r) * ldb + bcol);
        }
        __syncthreads();
        #pragma unroll
        for (int i = 0; i < 4; i++) {
            int r = arow + i * 32;
            As[acol + 0][r] = av[i].x; As[acol + 1][r] = av[i].y;
            As[acol + 2][r] = av[i].z; As[acol + 3][r] = av[i].w;
        }
        #pragma unroll
        for (int i = 0; i < 4; i++)
            *(float4*)&Bs[brow + i * 8][bcol] = bv[i];
        __syncthreads();

        #pragma unroll
        for (int kk = 0; kk < 32; kk++) {
            float4 a0 = *(const float4*)&As[kk][ty * 8];
            float4 a1 = *(const float4*)&As[kk][ty * 8 + 4];
            float4 b0 = *(const float4*)&Bs[kk][tx * 8];
            float4 b1 = *(const float4*)&Bs[kk][tx * 8 + 4];
            float a[8] = {a0.x, a0.y, a0.z, a0.w, a1.x, a1.y, a1.z, a1.w};
            float b[8] = {b0.x, b0.y, b0.z, b0.w, b1.x, b1.y, b1.z, b1.w};
            #pragma unroll
            for (int i = 0; i < 8; i++)
                #pragma unroll
                for (int j = 0; j < 8; j++)
                    acc[i][j] = fmaf(a[i], b[j], acc[i][j]);
        }
    }

    #pragma unroll
    for (int i = 0; i < 8; i++) {
        int row = crow0 + ty * 8 + i;
        #pragma unroll
        for (int j = 0; j < 8; j++) {
            int col = ccol0 + tx * 8 + j;
            float val = acc[i][j] * scale;
            if (EPI == 0) val = val / (1.0f + expf(-val));          // silu
            if (EPI == 2) val += R[(long)row * ldr_row + (long)col * ldr_col + r_off];
            C[(long)row * ldc_row + (long)col * ldc_col + c_off] = val;
        }
    }
}

// ---------------- orchestration ---------------------------------------------------
extern "C" void kernel_launch(void* const* d_in, const int* in_sizes, int n_in,
                              void* d_out, int out_size)
{
    const float* x  = (const float*)d_in[0];   // (16384, 512)
    const float* w1 = (const float*)d_in[1];   // (2, 384, 384)
    const float* w2 = (const float*)d_in[2];   // (2, 384, 768)
    const float* w0 = (const float*)d_in[3];   // (2, 384, 128)
    const float* wv = (const float*)d_in[4];   // (2, 256, 128)
    const float* g0 = (const float*)d_in[5];   // (128,)
    const float* g1 = (const float*)d_in[6];   // (128,)
    float* out = (float*)d_out;                // (16384, 512)

    float *sc, *h, *g, *sb, *vb, *vt;
    cudaGetSymbolAddress((void**)&sc, d_sc);
    cudaGetSymbolAddress((void**)&h,  d_h);
    cudaGetSymbolAddress((void**)&g,  d_g);
    cudaGetSymbolAddress((void**)&sb, d_s);
    cudaGetSymbolAddress((void**)&vb, d_v);
    cudaGetSymbolAddress((void**)&vt, d_vt);

    const float s384 = 1.0f / sqrtf(384.0f);
    const float s256 = 1.0f / 16.0f;           // 1/sqrt(256)

    const int eb = (NNODES * 128) / 256;       // elementwise blocks
    dim3 thr(256);
    dim3 grid1(3, NNODES / 128);               // N=384
    dim3 grid2(5, NNODES / 128);               // N=640 (skip dead 128 cols of w2)
    dim3 grid3(1, NNODES / 128);               // N=128
    dim3 grid4(1, NNODES / 128);               // N=128

    for (int layer = 0; layer < 2; layer++) {
        if (layer == 0)
            prep_kernel<<<eb, 256>>>(x, 512, x + 128, 512, sc, sb, vb, 1);
        else
            prep_kernel<<<eb, 256>>>(sb, 128, vb, 384, sc, nullptr, nullptr, 0);

        const float* W1 = w1 + (long)layer * 384 * 384;
        const float* W2 = w2 + (long)layer * 384 * 768;
        const float* W0 = w0 + (long)layer * 384 * 128;
        const float* WV = wv + (long)layer * 256 * 128;

        // h = silu(sc @ W1 / sqrt384)
        gemm_kernel<0, false><<<grid1, thr>>>(sc, 384, nullptr, 0, W1, 384,
                                              h, 384, 1, 0, nullptr, 0, 0, 0, 384, s384);
        // g = h @ W2[:, :640] / sqrt384
        gemm_kernel<1, false><<<grid2, thr>>>(h, 384, nullptr, 0, W2, 768,
                                              g, 640, 1, 0, nullptr, 0, 0, 0, 384, s384);
        // gated vec, transposed per-component
        gatevec_kernel<<<eb, 256>>>(sc, vb, g, vt);

        // s_out = s + (sc*g_s) @ W0 / sqrt384
        float* Cs = (layer == 0) ? sb : out;
        int ldcs = (layer == 0) ? 128 : 512;
        gemm_kernel<2, true><<<grid3, thr>>>(sc, 384, g, 640, W0, 128,
                                             Cs, ldcs, 1, 0, sb, 128, 1, 0, 384, s384);
        // v_out[:, c, d] = v + vecT[d] @ WV / 16
        for (int d = 0; d < 3; d++) {
            float* Cv = (layer == 0) ? vb : out;
            int ldcv  = (layer == 0) ? 384 : 512;
            int coff  = (layer == 0) ? d : 128 + d;
            gemm_kernel<2, false><<<grid4, thr>>>(vt + (long)d * NNODES * 256, 256,
                                                  nullptr, 0, WV, 128,
                                                  Cv, ldcv, 3, coff,
                                                  vb, 384, 3, d, 256, s256);
        }
        if (layer == 0) ln_kernel<<<NNODES, 128>>>(sb, vb, g0, g1);
    }
}

// round 5
// speedup vs baseline: 1.4562x; 1.4562x over previous
#include <cuda_runtime.h>
#include <cstdint>
#include <math.h>

#define NNODES 16384

// ═══════════════════════ scratch (static device globals) ═══════════════════════
__device__ float d_sc[(long)NNODES * 384];    // [s, s^2, |v|^2/sqrt3]
__device__ float d_h [(long)NNODES * 384];    // silu(sc @ w1 / sqrt384)
__device__ float d_g [(long)NNODES * 640];    // h @ w2[:, :640] / sqrt384
__device__ float d_s [(long)NNODES * 128];    // scalar state
__device__ float d_v [(long)NNODES * 384];    // vector state (N, C, 3)
__device__ float d_vt[3L * NNODES * 256];     // gated vec, transposed per d

// ═══════════════════════ elementwise kernels ═══════════════════════
__global__ void prep_kernel(const float* __restrict__ S, int ldS,
                            const float* __restrict__ V, int ldV,
                            float* __restrict__ sc,
                            float* __restrict__ sbuf, float* __restrict__ vbuf, int copy)
{
    int idx = blockIdx.x * blockDim.x + threadIdx.x;
    if (idx >= NNODES * 128) return;
    int n = idx >> 7, c = idx & 127;
    float s = S[(long)n * ldS + c];
    const float* vp = V + (long)n * ldV + 3 * c;
    float vx = vp[0], vy = vp[1], vz = vp[2];
    float* scp = sc + (long)n * 384 + c;
    scp[0] = s;
    scp[128] = s * s;
    scp[256] = (vx * vx + vy * vy + vz * vz) * 0.57735026918962576451f;
    if (copy) {
        sbuf[(long)n * 128 + c] = s;
        float* vb = vbuf + (long)n * 384 + 3 * c;
        vb[0] = vx; vb[1] = vy; vb[2] = vz;
    }
}

__global__ void gatevec_kernel(const float* __restrict__ sc, const float* __restrict__ vbuf,
                               const float* __restrict__ g, float* __restrict__ vecT)
{
    int idx = blockIdx.x * blockDim.x + threadIdx.x;
    if (idx >= NNODES * 128) return;
    int n = idx >> 7, m = idx & 127;
    float s = sc[(long)n * 384 + m];
    const float* vp = vbuf + (long)n * 384 + 3 * m;
    float gv1 = g[(long)n * 640 + 384 + m];
    float gv2 = g[(long)n * 640 + 512 + m];
    float c2 = 1.41421356237309514547f * s * gv2;
    #pragma unroll
    for (int d = 0; d < 3; d++) {
        float vd = vp[d];
        vecT[(long)d * NNODES * 256 + (long)n * 256 + m]       = vd * gv1;
        vecT[(long)d * NNODES * 256 + (long)n * 256 + 128 + m] = vd * c2;
    }
}

__device__ __forceinline__ float blk_red(float val, float* sh, int t)
{
    #pragma unroll
    for (int o = 16; o; o >>= 1) val += __shfl_xor_sync(0xffffffffu, val, o);
    if ((t & 31) == 0) sh[t >> 5] = val;
    __syncthreads();
    val = sh[0] + sh[1] + sh[2] + sh[3];
    __syncthreads();
    return val;
}

__global__ void ln_kernel(float* __restrict__ s, float* __restrict__ v,
                          const float* __restrict__ g0, const float* __restrict__ g1)
{
    __shared__ float sh[4];
    int n = blockIdx.x, t = threadIdx.x;
    float sv = s[(long)n * 128 + t];
    float mu = blk_red(sv, sh, t) * (1.0f / 128.0f);
    float dd = sv - mu;
    float var = blk_red(dd * dd, sh, t) * (1.0f / 128.0f);
    float sd = sqrtf(var + 1e-6f);
    float* vp = v + (long)n * 384 + 3 * t;
    float vx = vp[0], vy = vp[1], vz = vp[2];
    float msq = blk_red(vx * vx + vy * vy + vz * vz, sh, t) * (1.0f / 384.0f);
    float rms = sqrtf(msq + 1e-6f);
    s[(long)n * 128 + t] = dd / sd * g0[t];
    float scl = g1[t] / rms;
    vp[0] = vx * scl; vp[1] = vy * scl; vp[2] = vz * scl;
}

// ═══════════════════════ mma.sync tf32x3 GEMM ═══════════════════════
// base-ISA tensor path (compute_103-safe): m16n8k8 tf32 HMMA + cp.async.
// CTA tile 128x128, BK=32, 8 warps (2m x 4n), warp tile 64x32.
// A stored fp32 in SMEM [128][36] (pad), B [32][132] (pad); tf32 split in regs.

static constexpr int ASTRIDE = 36;                 // floats per A row (pad)
static constexpr int BSTRIDE = 132;                // floats per B row (pad)
static constexpr int A_ELEMS = 128 * ASTRIDE;      // 4608
static constexpr int B_ELEMS = 32 * BSTRIDE;       // 4224
static constexpr int STAGE   = A_ELEMS + B_ELEMS;  // 8832 floats
static constexpr uint32_t SMEM_BYTES = 2 * STAGE * 4;  // 70656

__device__ __forceinline__ uint32_t smem_u32(const void* p) {
    uint32_t a;
    asm("{ .reg .u64 t; cvta.to.shared.u64 t, %1; cvt.u32.u64 %0, t; }" : "=r"(a) : "l"(p));
    return a;
}
__device__ __forceinline__ void cp16(uint32_t dst, const float* src) {
    asm volatile("cp.async.cg.shared.global [%0], [%1], 16;" :: "r"(dst), "l"(src));
}
__device__ __forceinline__ uint32_t f2tf(float a) {
    uint32_t r;
    asm("cvt.rna.tf32.f32 %0, %1;" : "=r"(r) : "f"(a));
    return r;
}
__device__ __forceinline__ void tsplit(float a, uint32_t& hi, uint32_t& lo) {
    hi = f2tf(a);
    lo = f2tf(a - __uint_as_float(hi));
}
__device__ __forceinline__ void mma8(float* c, const uint32_t* a, const uint32_t* b) {
    asm volatile(
        "mma.sync.aligned.m16n8k8.row.col.f32.tf32.tf32.f32 "
        "{%0,%1,%2,%3},{%4,%5,%6,%7},{%8,%9},{%0,%1,%2,%3};"
        : "+f"(c[0]), "+f"(c[1]), "+f"(c[2]), "+f"(c[3])
        : "r"(a[0]), "r"(a[1]), "r"(a[2]), "r"(a[3]), "r"(b[0]), "r"(b[1]));
}

template<int EPI, bool GATED>
__global__ void __launch_bounds__(256)
mmagemm(const float* __restrict__ A, int lda, const float* __restrict__ A2, int lda2,
        const float* __restrict__ B, int ldb,
        float* __restrict__ C, int ldc_row, int ldc_col, int c_off,
        const float* __restrict__ R, int ldr_row, int ldr_col, int r_off,
        int K, float scale)
{
    extern __shared__ float sm[];
    const int t = threadIdx.x, lane = t & 31, w = t >> 5;
    const int g = lane >> 2, tig = lane & 3;
    const int wm = (w & 1) * 64, wn = (w >> 1) * 32;
    const int row0 = blockIdx.y * 128, col0 = blockIdx.x * 128;
    A += (long)row0 * lda;
    if (GATED) A2 += (long)row0 * lda2;
    B += col0;
    const uint32_t smb = smem_u32(sm);

    float c[16][4];
    #pragma unroll
    for (int i = 0; i < 16; i++) { c[i][0] = c[i][1] = c[i][2] = c[i][3] = 0.0f; }

    const int nch = K >> 5;

    // ---- async issue helpers (inlined per chunk) ----
    auto issue = [&](int ch) {
        const int kt = ch << 5, s = ch & 1;
        // B: 32 rows x 128 floats, 1024 float4 ops
        #pragma unroll
        for (int i = 0; i < 4; i++) {
            int idx = t + i * 256;
            int r = idx >> 5, c4 = (idx & 31) * 4;
            cp16(smb + (uint32_t)(s * STAGE + A_ELEMS + r * BSTRIDE + c4) * 4,
                 B + (long)(kt + r) * ldb + c4);
        }
        if (!GATED) {
            // A: 128 rows x 32 floats
            #pragma unroll
            for (int i = 0; i < 4; i++) {
                int idx = t + i * 256;
                int r = idx >> 3, c4 = (idx & 7) * 4;
                cp16(smb + (uint32_t)(s * STAGE + r * ASTRIDE + c4) * 4,
                     A + (long)r * lda + kt + c4);
            }
        }
        asm volatile("cp.async.commit_group;" ::: "memory");
        if (GATED) {
            const int ss = s;
            #pragma unroll
            for (int i = 0; i < 4; i++) {
                int idx = t + i * 256;
                int r = idx >> 3, c4 = (idx & 7) * 4;
                float4 a = *(const float4*)(A + (long)r * lda + kt + c4);
                float4 q = *(const float4*)(A2 + (long)r * lda2 + kt + c4);
                a.x *= q.x; a.y *= q.y; a.z *= q.z; a.w *= q.w;
                *(float4*)(sm + ss * STAGE + r * ASTRIDE + c4) = a;
            }
        }
    };

    issue(0);

    for (int ch = 0; ch < nch; ch++) {
        const bool more = (ch + 1 < nch);
        if (more) issue(ch + 1);
        if (more) asm volatile("cp.async.wait_group 1;" ::: "memory");
        else      asm volatile("cp.async.wait_group 0;" ::: "memory");
        __syncthreads();

        const float* As = sm + (ch & 1) * STAGE;
        const float* Bs = As + A_ELEMS;

        #pragma unroll
        for (int ks = 0; ks < 4; ks++) {
            const int k0 = ks * 8;
            uint32_t ahi[4][4], alo[4][4];
            #pragma unroll
            for (int mt = 0; mt < 4; mt++) {
                const float* ap = As + (wm + mt * 16 + g) * ASTRIDE + k0 + tig;
                tsplit(ap[0],               ahi[mt][0], alo[mt][0]);
                tsplit(ap[8 * ASTRIDE],     ahi[mt][1], alo[mt][1]);
                tsplit(ap[4],               ahi[mt][2], alo[mt][2]);
                tsplit(ap[8 * ASTRIDE + 4], ahi[mt][3], alo[mt][3]);
            }
            uint32_t bhi[4][2], blo[4][2];
            #pragma unroll
            for (int nt = 0; nt < 4; nt++) {
                const float* bp = Bs + (k0 + tig) * BSTRIDE + wn + nt * 8 + g;
                tsplit(bp[0],           bhi[nt][0], blo[nt][0]);
                tsplit(bp[4 * BSTRIDE], bhi[nt][1], blo[nt][1]);
            }
            #pragma unroll
            for (int mt = 0; mt < 4; mt++)
                #pragma unroll
                for (int nt = 0; nt < 4; nt++) {
                    mma8(c[mt * 4 + nt], ahi[mt], bhi[nt]);
                    mma8(c[mt * 4 + nt], alo[mt], bhi[nt]);
                    mma8(c[mt * 4 + nt], ahi[mt], blo[nt]);
                }
        }
        if (more) __syncthreads();   // release the buffer issue(ch+2) will write
    }

    // ---- epilogue straight from registers ----
    #pragma unroll
    for (int mt = 0; mt < 4; mt++)
        #pragma unroll
        for (int nt = 0; nt < 4; nt++) {
            const float* cf = c[mt * 4 + nt];
            const int r0 = row0 + wm + mt * 16 + g;
            const int cc = col0 + wn + nt * 8 + 2 * tig;
            #pragma unroll
            for (int hh = 0; hh < 2; hh++) {
                const int row = r0 + hh * 8;
                float v0 = cf[hh * 2 + 0] * scale;
                float v1 = cf[hh * 2 + 1] * scale;
                if (EPI == 0) {
                    v0 = v0 / (1.0f + expf(-v0));
                    v1 = v1 / (1.0f + expf(-v1));
                }
                if (ldc_col == 1) {
                    if (EPI == 2) {
                        const float2 rr = *(const float2*)&R[(long)row * ldr_row + cc];
                        v0 += rr.x; v1 += rr.y;
                    }
                    *(float2*)&C[(long)row * ldc_row + cc + c_off] = make_float2(v0, v1);
                } else {
                    if (EPI == 2) {
                        v0 += R[(long)row * ldr_row + (long)cc * ldr_col + r_off];
                        v1 += R[(long)row * ldr_row + (long)(cc + 1) * ldr_col + r_off];
                    }
                    C[(long)row * ldc_row + (long)cc * ldc_col + c_off] = v0;
                    C[(long)row * ldc_row + (long)(cc + 1) * ldc_col + c_off] = v1;
                }
            }
        }
}

// ═══════════════════════ orchestration ═══════════════════════
extern "C" void kernel_launch(void* const* d_in, const int* in_sizes, int n_in,
                              void* d_out, int out_size)
{
    const float* x  = (const float*)d_in[0];
    const float* w1 = (const float*)d_in[1];
    const float* w2 = (const float*)d_in[2];
    const float* w0 = (const float*)d_in[3];
    const float* wv = (const float*)d_in[4];
    const float* g0 = (const float*)d_in[5];
    const float* g1 = (const float*)d_in[6];
    float* out = (float*)d_out;

    float *sc, *h, *g, *sb, *vb, *vt;
    cudaGetSymbolAddress((void**)&sc, d_sc);
    cudaGetSymbolAddress((void**)&h,  d_h);
    cudaGetSymbolAddress((void**)&g,  d_g);
    cudaGetSymbolAddress((void**)&sb, d_s);
    cudaGetSymbolAddress((void**)&vb, d_v);
    cudaGetSymbolAddress((void**)&vt, d_vt);

    cudaFuncSetAttribute((const void*)mmagemm<0, false>, cudaFuncAttributeMaxDynamicSharedMemorySize, SMEM_BYTES);
    cudaFuncSetAttribute((const void*)mmagemm<1, false>, cudaFuncAttributeMaxDynamicSharedMemorySize, SMEM_BYTES);
    cudaFuncSetAttribute((const void*)mmagemm<2, true >, cudaFuncAttributeMaxDynamicSharedMemorySize, SMEM_BYTES);
    cudaFuncSetAttribute((const void*)mmagemm<2, false>, cudaFuncAttributeMaxDynamicSharedMemorySize, SMEM_BYTES);

    const float s384 = 1.0f / sqrtf(384.0f);
    const float s256 = 1.0f / 16.0f;

    const int eb = (NNODES * 128) / 256;
    dim3 thr(256);
    dim3 grid1(3, NNODES / 128);
    dim3 grid2(5, NNODES / 128);
    dim3 grid3(1, NNODES / 128);

    for (int layer = 0; layer < 2; layer++) {
        if (layer == 0)
            prep_kernel<<<eb, 256>>>(x, 512, x + 128, 512, sc, sb, vb, 1);
        else
            prep_kernel<<<eb, 256>>>(sb, 128, vb, 384, sc, nullptr, nullptr, 0);

        const float* W1 = w1 + (long)layer * 384 * 384;
        const float* W2 = w2 + (long)layer * 384 * 768;
        const float* W0 = w0 + (long)layer * 384 * 128;
        const float* WV = wv + (long)layer * 256 * 128;

        // h = silu(sc @ W1 / sqrt384)
        mmagemm<0, false><<<grid1, thr, SMEM_BYTES>>>(sc, 384, nullptr, 0, W1, 384,
                                                      h, 384, 1, 0, nullptr, 0, 0, 0, 384, s384);
        // g = h @ W2[:, :640] / sqrt384
        mmagemm<1, false><<<grid2, thr, SMEM_BYTES>>>(h, 384, nullptr, 0, W2, 768,
                                                      g, 640, 1, 0, nullptr, 0, 0, 0, 384, s384);
        gatevec_kernel<<<eb, 256>>>(sc, vb, g, vt);

        // s_out = s + (sc*g_s) @ W0 / sqrt384
        float* Cs = (layer == 0) ? sb : out;
        int ldcs = (layer == 0) ? 128 : 512;
        mmagemm<2, true><<<grid3, thr, SMEM_BYTES>>>(sc, 384, g, 640, W0, 128,
                                                     Cs, ldcs, 1, 0, sb, 128, 1, 0, 384, s384);
        // v_out[:, c, d] = v + vecT[d] @ WV / 16
        for (int d = 0; d < 3; d++) {
            float* Cv = (layer == 0) ? vb : out;
            int ldcv = (layer == 0) ? 384 : 512;
            int coff = (layer == 0) ? d : 128 + d;
            mmagemm<2, false><<<grid3, thr, SMEM_BYTES>>>(vt + (long)d * NNODES * 256, 256,
                                                          nullptr, 0, WV, 128,
                                                          Cv, ldcv, 3, coff,
                                                          vb, 384, 3, d, 256, s256);
        }
        if (layer == 0) ln_kernel<<<NNODES, 128>>>(sb, vb, g0, g1);
    }
}

// round 8
// speedup vs baseline: 1.8332x; 1.2588x over previous
#include <cuda_runtime.h>
#include <cuda_bf16.h>
#include <cstdint>
#include <math.h>

#define NNODES 16384

// ═══════════════════════ scratch (static device globals) ═══════════════════════
__device__ float d_sc[(long)NNODES * 384];    // [s, s^2, |v|^2/sqrt3]
__device__ float d_h [(long)NNODES * 384];    // silu(sc @ w1 / sqrt384)
__device__ float d_g [(long)NNODES * 640];    // cols 0..383: sc * g_s (gated)
__device__ float d_s [(long)NNODES * 128];    // scalar state
__device__ float d_v [(long)NNODES * 384];    // vector state (N, C, 3)
__device__ float d_vt[3L * NNODES * 256];     // gated vec, transposed per d

// ═══════════════════════ elementwise kernels ═══════════════════════
__global__ void prep_kernel(const float* __restrict__ S, int ldS,
                            const float* __restrict__ V, int ldV,
                            float* __restrict__ sc,
                            float* __restrict__ sbuf, float* __restrict__ vbuf)
{
    int idx = blockIdx.x * blockDim.x + threadIdx.x;
    if (idx >= NNODES * 128) return;
    int n = idx >> 7, c = idx & 127;
    float s = S[(long)n * ldS + c];
    const float* vp = V + (long)n * ldV + 3 * c;
    float vx = vp[0], vy = vp[1], vz = vp[2];
    float* scp = sc + (long)n * 384 + c;
    scp[0] = s;
    scp[128] = s * s;
    scp[256] = (vx * vx + vy * vy + vz * vz) * 0.57735026918962576451f;
    sbuf[(long)n * 128 + c] = s;
    float* vb = vbuf + (long)n * 384 + 3 * c;
    vb[0] = vx; vb[1] = vy; vb[2] = vz;
}

__device__ __forceinline__ float blk_red(float val, float* sh, int t)
{
    #pragma unroll
    for (int o = 16; o; o >>= 1) val += __shfl_xor_sync(0xffffffffu, val, o);
    if ((t & 31) == 0) sh[t >> 5] = val;
    __syncthreads();
    val = sh[0] + sh[1] + sh[2] + sh[3];
    __syncthreads();
    return val;
}

// layernorm fused with next layer's prep (writes sc directly)
__global__ void ln_kernel(float* __restrict__ s, float* __restrict__ v,
                          const float* __restrict__ g0, const float* __restrict__ g1,
                          float* __restrict__ sc)
{
    __shared__ float sh[4];
    int n = blockIdx.x, t = threadIdx.x;
    float sv = s[(long)n * 128 + t];
    float mu = blk_red(sv, sh, t) * (1.0f / 128.0f);
    float dd = sv - mu;
    float var = blk_red(dd * dd, sh, t) * (1.0f / 128.0f);
    float sd = sqrtf(var + 1e-6f);
    float* vp = v + (long)n * 384 + 3 * t;
    float vx = vp[0], vy = vp[1], vz = vp[2];
    float msq = blk_red(vx * vx + vy * vy + vz * vz, sh, t) * (1.0f / 384.0f);
    float rms = sqrtf(msq + 1e-6f);
    float sn = dd / sd * g0[t];
    s[(long)n * 128 + t] = sn;
    float scl = g1[t] / rms;
    float nx = vx * scl, ny = vy * scl, nz = vz * scl;
    vp[0] = nx; vp[1] = ny; vp[2] = nz;
    float* scp = sc + (long)n * 384 + t;
    scp[0] = sn;
    scp[128] = sn * sn;
    scp[256] = (nx * nx + ny * ny + nz * nz) * 0.57735026918962576451f;
}

// ═══════════════════════ mma.sync bf16x3 GEMM ═══════════════════════
// base-ISA tensor path (compute_103-safe): m16n8k16 bf16 HMMA + cp.async.
// CTA tile 128x128, BK=32, 8 warps (2m x 4n), warp tile 64x32.
// fp32 staged in SMEM; hi/lo bf16 split at fragment load.

static constexpr int ASTRIDE = 36;
static constexpr int BSTRIDE = 132;
static constexpr int A_ELEMS = 128 * ASTRIDE;
static constexpr int B_ELEMS = 32 * BSTRIDE;
static constexpr int STAGE   = A_ELEMS + B_ELEMS;
static constexpr uint32_t SMEM_BYTES = 2 * STAGE * 4;

__device__ __forceinline__ uint32_t smem_u32(const void* p) {
    uint32_t a;
    asm("{ .reg .u64 t; cvta.to.shared.u64 t, %1; cvt.u32.u64 %0, t; }" : "=r"(a) : "l"(p));
    return a;
}
__device__ __forceinline__ void cp16(uint32_t dst, const float* src) {
    asm volatile("cp.async.cg.shared.global [%0], [%1], 16;" :: "r"(dst), "l"(src));
}
// split (e0,e1) into packed-bf16 hi pair (e0 in lower 16) and residual lo pair
__device__ __forceinline__ void bsplit2(float e0, float e1, uint32_t& hi, uint32_t& lo) {
    __nv_bfloat162 hp = __floats2bfloat162_rn(e0, e1);
    uint32_t h = *reinterpret_cast<uint32_t*>(&hp);
    float h0 = __uint_as_float(h << 16);
    float h1 = __uint_as_float(h & 0xffff0000u);
    __nv_bfloat162 lp = __floats2bfloat162_rn(e0 - h0, e1 - h1);
    hi = h;
    lo = *reinterpret_cast<uint32_t*>(&lp);
}
__device__ __forceinline__ void mma16(float* c, const uint32_t* a, const uint32_t* b) {
    asm volatile(
        "mma.sync.aligned.m16n8k16.row.col.f32.bf16.bf16.f32 "
        "{%0,%1,%2,%3},{%4,%5,%6,%7},{%8,%9},{%0,%1,%2,%3};"
        : "+f"(c[0]), "+f"(c[1]), "+f"(c[2]), "+f"(c[3])
        : "r"(a[0]), "r"(a[1]), "r"(a[2]), "r"(a[3]), "r"(b[0]), "r"(b[1]));
}

// EPI: 0 = silu -> C ; 2 = +R -> C (strided ok) ; 3 = GEMM2 gate-fuse
template<int EPI>
__global__ void __launch_bounds__(256)
mmagemm(const float* __restrict__ A0, int lda, long zsA,
        const float* __restrict__ B0, int ldb,
        float* __restrict__ C, int ldc_row, int ldc_col, int c_off_,
        const float* __restrict__ R, int ldr_row, int ldr_col, int r_off_,
        const float* __restrict__ scb, const float* __restrict__ vbuf,
        float* __restrict__ vtbuf,
        int K, float scale)
{
    extern __shared__ float sm[];
    const int t = threadIdx.x, lane = t & 31, w = t >> 5;
    const int g = lane >> 2, tig = lane & 3;
    const int wm = (w & 1) * 64, wn = (w >> 1) * 32;
    const int row0 = blockIdx.y * 128, col0 = blockIdx.x * 128;
    const int dz = blockIdx.z;
    const float* A = A0 + (long)row0 * lda + (long)dz * zsA;
    const float* B = B0 + col0;
    const int c_off = c_off_ + (zsA ? dz : 0);
    const int r_off = r_off_ + (zsA ? dz : 0);
    const uint32_t smb = smem_u32(sm);

    float c[16][4];
    #pragma unroll
    for (int i = 0; i < 16; i++) { c[i][0] = c[i][1] = c[i][2] = c[i][3] = 0.0f; }

    const int nch = K >> 5;

    auto issue = [&](int ch) {
        const int kt = ch << 5, s = ch & 1;
        #pragma unroll
        for (int i = 0; i < 4; i++) {
            int idx = t + i * 256;
            int r = idx >> 5, c4 = (idx & 31) * 4;
            cp16(smb + (uint32_t)(s * STAGE + A_ELEMS + r * BSTRIDE + c4) * 4,
                 B + (long)(kt + r) * ldb + c4);
        }
        #pragma unroll
        for (int i = 0; i < 4; i++) {
            int idx = t + i * 256;
            int r = idx >> 3, c4 = (idx & 7) * 4;
            cp16(smb + (uint32_t)(s * STAGE + r * ASTRIDE + c4) * 4,
                 A + (long)r * lda + kt + c4);
        }
        asm volatile("cp.async.commit_group;" ::: "memory");
    };

    issue(0);

    for (int ch = 0; ch < nch; ch++) {
        const bool more = (ch + 1 < nch);
        if (more) issue(ch + 1);
        if (more) asm volatile("cp.async.wait_group 1;" ::: "memory");
        else      asm volatile("cp.async.wait_group 0;" ::: "memory");
        __syncthreads();

        const float* As = sm + (ch & 1) * STAGE;
        const float* Bs = As + A_ELEMS;

        #pragma unroll
        for (int ks = 0; ks < 2; ks++) {
            const int k0 = ks * 16;
            uint32_t ahi[4][4], alo[4][4];
            #pragma unroll
            for (int mt = 0; mt < 4; mt++) {
                const float* ap = As + (wm + mt * 16 + g) * ASTRIDE + k0 + 2 * tig;
                float2 p0 = *(const float2*)(ap);
                float2 p1 = *(const float2*)(ap + 8 * ASTRIDE);
                float2 p2 = *(const float2*)(ap + 8);
                float2 p3 = *(const float2*)(ap + 8 * ASTRIDE + 8);
                bsplit2(p0.x, p0.y, ahi[mt][0], alo[mt][0]);
                bsplit2(p1.x, p1.y, ahi[mt][1], alo[mt][1]);
                bsplit2(p2.x, p2.y, ahi[mt][2], alo[mt][2]);
                bsplit2(p3.x, p3.y, ahi[mt][3], alo[mt][3]);
            }
            uint32_t bhi[4][2], blo[4][2];
            #pragma unroll
            for (int nt = 0; nt < 4; nt++) {
                const float* bp = Bs + (k0 + 2 * tig) * BSTRIDE + wn + nt * 8 + g;
                bsplit2(bp[0], bp[BSTRIDE], bhi[nt][0], blo[nt][0]);
                bsplit2(bp[8 * BSTRIDE], bp[9 * BSTRIDE], bhi[nt][1], blo[nt][1]);
            }
            #pragma unroll
            for (int mt = 0; mt < 4; mt++)
                #pragma unroll
                for (int nt = 0; nt < 4; nt++) {
                    mma16(c[mt * 4 + nt], ahi[mt], bhi[nt]);
                    mma16(c[mt * 4 + nt], alo[mt], bhi[nt]);
                    mma16(c[mt * 4 + nt], ahi[mt], blo[nt]);
                }
        }
        if (more) __syncthreads();
    }

    // ---- epilogue straight from registers ----
    #pragma unroll
    for (int mt = 0; mt < 4; mt++)
        #pragma unroll
        for (int nt = 0; nt < 4; nt++) {
            const float* cf = c[mt * 4 + nt];
            const int rb = row0 + wm + mt * 16 + g;
            const int cc = col0 + wn + nt * 8 + 2 * tig;
            #pragma unroll
            for (int hh = 0; hh < 2; hh++) {
                const int row = rb + hh * 8;
                float v0 = cf[hh * 2 + 0] * scale;
                float v1 = cf[hh * 2 + 1] * scale;
                if (EPI == 0) {
                    v0 = v0 / (1.0f + expf(-v0));
                    v1 = v1 / (1.0f + expf(-v1));
                    *(float2*)&C[(long)row * ldc_row + cc] = make_float2(v0, v1);
                } else if (EPI == 2) {
                    if (ldc_col == 1) {
                        const float2 rr = *(const float2*)&R[(long)row * ldr_row + cc];
                        *(float2*)&C[(long)row * ldc_row + cc + c_off] =
                            make_float2(v0 + rr.x, v1 + rr.y);
                    } else {
                        v0 += R[(long)row * ldr_row + (long)cc * ldr_col + r_off];
                        v1 += R[(long)row * ldr_row + (long)(cc + 1) * ldr_col + r_off];
                        C[(long)row * ldc_row + (long)cc * ldc_col + c_off] = v0;
                        C[(long)row * ldc_row + (long)(cc + 1) * ldc_col + c_off] = v1;
                    }
                } else { // EPI == 3: gate-fuse
                    if (col0 < 384) {
                        const float2 ss = *(const float2*)&scb[(long)row * 384 + cc];
                        *(float2*)&C[(long)row * 640 + cc] = make_float2(v0 * ss.x, v1 * ss.y);
                    } else if (col0 == 384) {
                        const int m = cc - 384;
                        const float* vp = vbuf + (long)row * 384 + 3 * m;
                        #pragma unroll
                        for (int d = 0; d < 3; d++) {
                            *(float2*)&vtbuf[(long)d * NNODES * 256 + (long)row * 256 + m] =
                                make_float2(vp[d] * v0, vp[3 + d] * v1);
                        }
                    } else {
                        const int m = cc - 512;
                        const float a0 = 1.41421356237309514547f * scb[(long)row * 384 + m] * v0;
                        const float a1 = 1.41421356237309514547f * scb[(long)row * 384 + m + 1] * v1;
                        const float* vp = vbuf + (long)row * 384 + 3 * m;
                        #pragma unroll
                        for (int d = 0; d < 3; d++) {
                            *(float2*)&vtbuf[(long)d * NNODES * 256 + (long)row * 256 + 128 + m] =
                                make_float2(vp[d] * a0, vp[3 + d] * a1);
                        }
                    }
                }
            }
        }
}

// ═══════════════════════ orchestration ═══════════════════════
extern "C" void kernel_launch(void* const* d_in, const int* in_sizes, int n_in,
                              void* d_out, int out_size)
{
    const float* x  = (const float*)d_in[0];
    const float* w1 = (const float*)d_in[1];
    const float* w2 = (const float*)d_in[2];
    const float* w0 = (const float*)d_in[3];
    const float* wv = (const float*)d_in[4];
    const float* g0 = (const float*)d_in[5];
    const float* g1 = (const float*)d_in[6];
    float* out = (float*)d_out;

    float *sc, *h, *g, *sb, *vb, *vt;
    cudaGetSymbolAddress((void**)&sc, d_sc);
    cudaGetSymbolAddress((void**)&h,  d_h);
    cudaGetSymbolAddress((void**)&g,  d_g);
    cudaGetSymbolAddress((void**)&sb, d_s);
    cudaGetSymbolAddress((void**)&vb, d_v);
    cudaGetSymbolAddress((void**)&vt, d_vt);

    cudaFuncSetAttribute((const void*)mmagemm<0>, cudaFuncAttributeMaxDynamicSharedMemorySize, SMEM_BYTES);
    cudaFuncSetAttribute((const void*)mmagemm<2>, cudaFuncAttributeMaxDynamicSharedMemorySize, SMEM_BYTES);
    cudaFuncSetAttribute((const void*)mmagemm<3>, cudaFuncAttributeMaxDynamicSharedMemorySize, SMEM_BYTES);

    const float s384 = 1.0f / sqrtf(384.0f);
    const float s256 = 1.0f / 16.0f;

    const int eb = (NNODES * 128) / 256;
    dim3 thr(256);
    dim3 grid1(3, NNODES / 128);       // N=384
    dim3 grid2(5, NNODES / 128);       // N=640
    dim3 grid3(1, NNODES / 128);       // N=128
    dim3 gridv(1, NNODES / 128, 3);    // N=128, z = vector component

    prep_kernel<<<eb, 256>>>(x, 512, x + 128, 512, sc, sb, vb);

    for (int layer = 0; layer < 2; layer++) {
        const float* W1 = w1 + (long)layer * 384 * 384;
        const float* W2 = w2 + (long)layer * 384 * 768;
        const float* W0 = w0 + (long)layer * 384 * 128;
        const float* WV = wv + (long)layer * 256 * 128;

        // h = silu(sc @ W1 / sqrt384)
        mmagemm<0><<<grid1, thr, SMEM_BYTES>>>(sc, 384, 0, W1, 384,
                                               h, 384, 1, 0, nullptr, 0, 0, 0,
                                               nullptr, nullptr, nullptr, 384, s384);
        // g-GEMM with fused gating: cols 0..383 -> g = sc*g_s ; cols 384..639 -> vt
        mmagemm<3><<<grid2, thr, SMEM_BYTES>>>(h, 384, 0, W2, 768,
                                               g, 640, 1, 0, nullptr, 0, 0, 0,
                                               sc, vb, vt, 384, s384);
        // s_out = s + g(ated sc) @ W0 / sqrt384
        float* Cs = (layer == 0) ? sb : out;
        int ldcs = (layer == 0) ? 128 : 512;
        mmagemm<2><<<grid3, thr, SMEM_BYTES>>>(g, 640, 0, W0, 128,
                                               Cs, ldcs, 1, 0, sb, 128, 1, 0,
                                               nullptr, nullptr, nullptr, 384, s384);
        // v_out[:, c, d] = v + vt[d] @ WV / 16   (z-dim = d)
        float* Cv = (layer == 0) ? vb : out;
        int ldcv = (layer == 0) ? 384 : 512;
        int coff = (layer == 0) ? 0 : 128;
        mmagemm<2><<<gridv, thr, SMEM_BYTES>>>(vt, 256, (long)NNODES * 256, WV, 128,
                                               Cv, ldcv, 3, coff, vb, 384, 3, 0,
                                               nullptr, nullptr, nullptr, 256, s256);
        if (layer == 0) ln_kernel<<<NNODES, 128>>>(sb, vb, g0, g1, sc);
    }
}

// round 11
// speedup vs baseline: 1.8376x; 1.0024x over previous
#include <cuda_runtime.h>
#include <cuda_bf16.h>
#include <cstdint>
#include <math.h>

#define NNODES 16384

// ═══════════ scratch: packed bf16 hi/lo planes (u32 = 2 k-consecutive bf16) ═══════════
__device__ uint32_t d_schi[(long)NNODES * 192], d_sclo[(long)NNODES * 192];
__device__ uint32_t d_hhi [(long)NNODES * 192], d_hlo [(long)NNODES * 192];
__device__ uint32_t d_ghi [(long)NNODES * 192], d_glo [(long)NNODES * 192];
__device__ uint32_t d_vthi[3L * NNODES * 128],  d_vtlo[3L * NNODES * 128];
__device__ uint32_t d_w1hi[2L * 384 * 192], d_w1lo[2L * 384 * 192];
__device__ uint32_t d_w2hi[2L * 640 * 192], d_w2lo[2L * 640 * 192];
__device__ uint32_t d_w0hi[2L * 128 * 192], d_w0lo[2L * 128 * 192];
__device__ uint32_t d_wvhi[2L * 128 * 128], d_wvlo[2L * 128 * 128];
__device__ float d_scf[(long)NNODES * 384];   // fp32 sc (for gating epilogue)
__device__ float d_s  [(long)NNODES * 128];   // scalar state fp32
__device__ float d_v  [(long)NNODES * 384];   // vector state fp32 (N, C, 3)

// ═══════════ helpers ═══════════
__device__ __forceinline__ uint32_t smem_u32(const void* p) {
    uint32_t a;
    asm("{ .reg .u64 t; cvta.to.shared.u64 t, %1; cvt.u32.u64 %0, t; }" : "=r"(a) : "l"(p));
    return a;
}
__device__ __forceinline__ void cp16(uint32_t dst, const void* src) {
    asm volatile("cp.async.cg.shared.global [%0], [%1], 16;" :: "r"(dst), "l"(src));
}
__device__ __forceinline__ void bsplit2(float e0, float e1, uint32_t& hi, uint32_t& lo) {
    __nv_bfloat162 hp = __floats2bfloat162_rn(e0, e1);
    uint32_t h = *reinterpret_cast<uint32_t*>(&hp);
    float h0 = __uint_as_float(h << 16);
    float h1 = __uint_as_float(h & 0xffff0000u);
    __nv_bfloat162 lp = __floats2bfloat162_rn(e0 - h0, e1 - h1);
    hi = h;
    lo = *reinterpret_cast<uint32_t*>(&lp);
}
__device__ __forceinline__ void mma16(float* c, const uint32_t* a, const uint32_t* b) {
    asm volatile(
        "mma.sync.aligned.m16n8k16.row.col.f32.bf16.bf16.f32 "
        "{%0,%1,%2,%3},{%4,%5,%6,%7},{%8,%9},{%0,%1,%2,%3};"
        : "+f"(c[0]), "+f"(c[1]), "+f"(c[2]), "+f"(c[3])
        : "r"(a[0]), "r"(a[1]), "r"(a[2]), "r"(a[3]), "r"(b[0]), "r"(b[1]));
}

// ═══════════ weight pre-split: fp32 [K][N] -> bf16 hi/lo planes [N][K/2] u32 ═══════════
__global__ void wsplit_kernel(const float* __restrict__ w1, const float* __restrict__ w2,
                              const float* __restrict__ w0, const float* __restrict__ wv)
{
    const int z = blockIdx.y, wsel = z & 3, layer = z >> 2;
    const float* W; int ldw, K2, N; uint32_t *dhi, *dlo;
    if (wsel == 0) { W = w1 + (long)layer * 384 * 384; ldw = 384; K2 = 192; N = 384;
                     dhi = d_w1hi + (long)layer * 384 * 192; dlo = d_w1lo + (long)layer * 384 * 192; }
    else if (wsel == 1) { W = w2 + (long)layer * 384 * 768; ldw = 768; K2 = 192; N = 640;
                     dhi = d_w2hi + (long)layer * 640 * 192; dlo = d_w2lo + (long)layer * 640 * 192; }
    else if (wsel == 2) { W = w0 + (long)layer * 384 * 128; ldw = 128; K2 = 192; N = 128;
                     dhi = d_w0hi + (long)layer * 128 * 192; dlo = d_w0lo + (long)layer * 128 * 192; }
    else { W = wv + (long)layer * 256 * 128; ldw = 128; K2 = 128; N = 128;
                     dhi = d_wvhi + (long)layer * 128 * 128; dlo = d_wvlo + (long)layer * 128 * 128; }
    int idx = blockIdx.x * 256 + threadIdx.x;
    if (idx >= N * K2) return;
    int n = idx / K2, k2 = idx % K2;
    float f0 = W[(long)(2 * k2) * ldw + n];
    float f1 = W[(long)(2 * k2 + 1) * ldw + n];
    uint32_t hi, lo;
    bsplit2(f0, f1, hi, lo);
    dhi[(long)n * K2 + k2] = hi;
    dlo[(long)n * K2 + k2] = lo;
}

// ═══════════ prep: x -> sc planes + scf + state ═══════════
__global__ void prep_kernel(const float* __restrict__ x)
{
    int idx = blockIdx.x * blockDim.x + threadIdx.x;
    if (idx >= NNODES * 64) return;
    int n = idx >> 6, c2 = idx & 63, c0 = 2 * c2;
    float2 s2 = *(const float2*)&x[(long)n * 512 + c0];
    const float* xv = x + (long)n * 512 + 128 + 3 * c0;
    float2 a = *(const float2*)(xv), b = *(const float2*)(xv + 2), cc = *(const float2*)(xv + 4);
    float vv0 = (a.x * a.x + a.y * a.y + b.x * b.x) * 0.57735026918962576451f;
    float vv1 = (b.y * b.y + cc.x * cc.x + cc.y * cc.y) * 0.57735026918962576451f;
    float ss0 = s2.x * s2.x, ss1 = s2.y * s2.y;
    float* scf = d_scf + (long)n * 384;
    *(float2*)&scf[c0] = s2;
    *(float2*)&scf[128 + c0] = make_float2(ss0, ss1);
    *(float2*)&scf[256 + c0] = make_float2(vv0, vv1);
    uint32_t hi, lo;
    long pb = (long)n * 192 + c2;
    bsplit2(s2.x, s2.y, hi, lo);  d_schi[pb] = hi;       d_sclo[pb] = lo;
    bsplit2(ss0, ss1, hi, lo);    d_schi[pb + 64] = hi;  d_sclo[pb + 64] = lo;
    bsplit2(vv0, vv1, hi, lo);    d_schi[pb + 128] = hi; d_sclo[pb + 128] = lo;
    *(float2*)&d_s[(long)n * 128 + c0] = s2;
    float* vb = d_v + (long)n * 384 + 3 * c0;
    *(float2*)(vb) = a; *(float2*)(vb + 2) = b; *(float2*)(vb + 4) = cc;
}

// ═══════════ equivariant layernorm (64 thr/node) fused with next prep ═══════════
__device__ __forceinline__ float red64(float v, float* sh, int t)
{
    #pragma unroll
    for (int o = 16; o; o >>= 1) v += __shfl_xor_sync(0xffffffffu, v, o);
    if ((t & 31) == 0) sh[t >> 5] = v;
    __syncthreads();
    v = sh[0] + sh[1];
    __syncthreads();
    return v;
}

__global__ void ln_kernel(const float* __restrict__ g0, const float* __restrict__ g1)
{
    __shared__ float sh[2];
    int n = blockIdx.x, t = threadIdx.x, c0 = 2 * t;
    float s0 = d_s[(long)n * 128 + c0], s1 = d_s[(long)n * 128 + c0 + 1];
    float mu = red64(s0 + s1, sh, t) * (1.0f / 128.0f);
    float dd0 = s0 - mu, dd1 = s1 - mu;
    float var = red64(dd0 * dd0 + dd1 * dd1, sh, t) * (1.0f / 128.0f);
    float sd = sqrtf(var + 1e-6f);
    float* vp = d_v + (long)n * 384 + 3 * c0;
    float v0 = vp[0], v1 = vp[1], v2 = vp[2], v3 = vp[3], v4 = vp[4], v5 = vp[5];
    float msq = red64(v0*v0 + v1*v1 + v2*v2 + v3*v3 + v4*v4 + v5*v5, sh, t) * (1.0f / 384.0f);
    float rms = sqrtf(msq + 1e-6f);
    float sn0 = dd0 / sd * g0[c0], sn1 = dd1 / sd * g0[c0 + 1];
    d_s[(long)n * 128 + c0] = sn0; d_s[(long)n * 128 + c0 + 1] = sn1;
    float sc0 = g1[c0] / rms, sc1 = g1[c0 + 1] / rms;
    float nx0 = v0 * sc0, ny0 = v1 * sc0, nz0 = v2 * sc0;
    float nx1 = v3 * sc1, ny1 = v4 * sc1, nz1 = v5 * sc1;
    vp[0] = nx0; vp[1] = ny0; vp[2] = nz0; vp[3] = nx1; vp[4] = ny1; vp[5] = nz1;
    float vv0 = (nx0*nx0 + ny0*ny0 + nz0*nz0) * 0.57735026918962576451f;
    float vv1 = (nx1*nx1 + ny1*ny1 + nz1*nz1) * 0.57735026918962576451f;
    float* scf = d_scf + (long)n * 384;
    scf[c0] = sn0; scf[c0 + 1] = sn1;
    scf[128 + c0] = sn0 * sn0; scf[128 + c0 + 1] = sn1 * sn1;
    scf[256 + c0] = vv0; scf[256 + c0 + 1] = vv1;
    uint32_t hi, lo;
    long pb = (long)n * 192 + t;
    bsplit2(sn0, sn1, hi, lo);          d_schi[pb] = hi;       d_sclo[pb] = lo;
    bsplit2(sn0*sn0, sn1*sn1, hi, lo);  d_schi[pb + 64] = hi;  d_sclo[pb + 64] = lo;
    bsplit2(vv0, vv1, hi, lo);          d_schi[pb + 128] = hi; d_sclo[pb + 128] = lo;
}

// ═══════════ pure-bf16 mainloop (shared by all GEMMs) ═══════════
// SMEM per stage (u32): Ahi[128][20] | Alo | Bhi | Blo ; 16 data u32 + 4 pad per row.
static constexpr int ST = 20;
static constexpr int OFF_ALO = 128 * ST;
static constexpr int OFF_BHI = 2 * 128 * ST;
static constexpr int OFF_BLO = 3 * 128 * ST;
static constexpr int STAGE32 = 4 * 128 * ST;
static constexpr uint32_t SMEM_BYTES = 2 * STAGE32 * 4;   // 81920

__device__ __forceinline__ void bf16_loop(
    const uint32_t* __restrict__ Ahi, const uint32_t* __restrict__ Alo, int lda32,
    const uint32_t* __restrict__ Bhi, const uint32_t* __restrict__ Blo, int ldb32,
    int nch, uint32_t* sm, float (*cacc)[4],
    int t, int wm, int wn, int g, int tig)
{
    const uint32_t smb = smem_u32(sm);
    {
        const uint32_t s0 = smb;
        #pragma unroll
        for (int i = 0; i < 2; i++) {
            int idx = t + i * 256;
            int r = idx >> 2, c4 = (idx & 3) * 4;
            cp16(s0 + (uint32_t)(r * ST + c4) * 4u,           Ahi + (long)r * lda32 + c4);
            cp16(s0 + (uint32_t)(OFF_ALO + r * ST + c4) * 4u, Alo + (long)r * lda32 + c4);
            cp16(s0 + (uint32_t)(OFF_BHI + r * ST + c4) * 4u, Bhi + (long)r * ldb32 + c4);
            cp16(s0 + (uint32_t)(OFF_BLO + r * ST + c4) * 4u, Blo + (long)r * ldb32 + c4);
        }
        asm volatile("cp.async.commit_group;" ::: "memory");
    }
    for (int ch = 0; ch < nch; ch++) {
        const bool more = (ch + 1 < nch);
        if (more) {
            const int kt = (ch + 1) * 16;
            const uint32_t s0 = smb + (uint32_t)(((ch + 1) & 1) * STAGE32) * 4u;
            #pragma unroll
            for (int i = 0; i < 2; i++) {
                int idx = t + i * 256;
                int r = idx >> 2, c4 = (idx & 3) * 4;
                cp16(s0 + (uint32_t)(r * ST + c4) * 4u,           Ahi + (long)r * lda32 + kt + c4);
                cp16(s0 + (uint32_t)(OFF_ALO + r * ST + c4) * 4u, Alo + (long)r * lda32 + kt + c4);
                cp16(s0 + (uint32_t)(OFF_BHI + r * ST + c4) * 4u, Bhi + (long)r * ldb32 + kt + c4);
                cp16(s0 + (uint32_t)(OFF_BLO + r * ST + c4) * 4u, Blo + (long)r * ldb32 + kt + c4);
            }
            asm volatile("cp.async.commit_group;" ::: "memory");
            asm volatile("cp.async.wait_group 1;" ::: "memory");
        } else {
            asm volatile("cp.async.wait_group 0;" ::: "memory");
        }
        __syncthreads();
        const uint32_t* As = sm + (ch & 1) * STAGE32;
        const uint32_t* Al = As + OFF_ALO;
        const uint32_t* Bs = As + OFF_BHI;
        const uint32_t* Bl = As + OFF_BLO;
        #pragma unroll
        for (int ks = 0; ks < 2; ks++) {
            const int kb = ks * 8 + tig;
            uint32_t ah[4][4], al[4][4];
            #pragma unroll
            for (int mt = 0; mt < 4; mt++) {
                int base = (wm + mt * 16 + g) * ST + kb;
                ah[mt][0] = As[base];              al[mt][0] = Al[base];
                ah[mt][1] = As[base + 8 * ST];     al[mt][1] = Al[base + 8 * ST];
                ah[mt][2] = As[base + 4];          al[mt][2] = Al[base + 4];
                ah[mt][3] = As[base + 8 * ST + 4]; al[mt][3] = Al[base + 8 * ST + 4];
            }
            uint32_t bh[4][2], bl[4][2];
            #pragma unroll
            for (int nt = 0; nt < 4; nt++) {
                int base = (wn + nt * 8 + g) * ST + kb;
                bh[nt][0] = Bs[base];     bl[nt][0] = Bl[base];
                bh[nt][1] = Bs[base + 4]; bl[nt][1] = Bl[base + 4];
            }
            #pragma unroll
            for (int mt = 0; mt < 4; mt++)
                #pragma unroll
                for (int nt = 0; nt < 4; nt++) {
                    mma16(cacc[mt * 4 + nt], ah[mt], bh[nt]);
                    mma16(cacc[mt * 4 + nt], al[mt], bh[nt]);
                    mma16(cacc[mt * 4 + nt], ah[mt], bl[nt]);
                }
        }
        if (more) __syncthreads();
    }
}

#define GEMM_PROLOG \
    extern __shared__ uint32_t smu[]; \
    const int t = threadIdx.x, lane = t & 31, w = t >> 5; \
    const int g = lane >> 2, tig = lane & 3; \
    const int wm = (w & 1) * 64, wn = (w >> 1) * 32; \
    float cacc[16][4]; \
    _Pragma("unroll") \
    for (int i = 0; i < 16; i++) { cacc[i][0] = cacc[i][1] = cacc[i][2] = cacc[i][3] = 0.0f; }

#define EPI_LOOP(...) \
    _Pragma("unroll") \
    for (int mt = 0; mt < 4; mt++) \
        _Pragma("unroll") \
        for (int nt = 0; nt < 4; nt++) { \
            const float* cf = cacc[mt * 4 + nt]; \
            const int rb = row0 + wm + mt * 16 + g; \
            const int cc = col0 + wn + nt * 8 + 2 * tig; \
            _Pragma("unroll") \
            for (int hh = 0; hh < 2; hh++) { \
                const int row = rb + hh * 8; \
                float v0 = cf[hh * 2 + 0] * scale; \
                float v1 = cf[hh * 2 + 1] * scale; \
                __VA_ARGS__ \
            } \
        }

// GEMM1: h = silu(sc @ W1 / sqrt384) -> h planes
__global__ void __launch_bounds__(256)
gemm1_kernel(const uint32_t* __restrict__ Bhi, const uint32_t* __restrict__ Blo, float scale)
{
    GEMM_PROLOG
    const int row0 = blockIdx.y * 128, col0 = blockIdx.x * 128;
    bf16_loop(d_schi + (long)row0 * 192, d_sclo + (long)row0 * 192, 192,
              Bhi + (long)col0 * 192, Blo + (long)col0 * 192, 192,
              12, smu, cacc, t, wm, wn, g, tig);
    EPI_LOOP(
        v0 = v0 / (1.0f + expf(-v0));
        v1 = v1 / (1.0f + expf(-v1));
        uint32_t hi, lo;
        bsplit2(v0, v1, hi, lo);
        d_hhi[(long)row * 192 + (cc >> 1)] = hi;
        d_hlo[(long)row * 192 + (cc >> 1)] = lo;
    )
}

// GEMM2: g = h @ W2[:, :640] / sqrt384, fused gating -> g planes + vt planes
__global__ void __launch_bounds__(256)
gemm2_kernel(const uint32_t* __restrict__ Bhi, const uint32_t* __restrict__ Blo, float scale)
{
    GEMM_PROLOG
    const int row0 = blockIdx.y * 128, col0 = blockIdx.x * 128;
    bf16_loop(d_hhi + (long)row0 * 192, d_hlo + (long)row0 * 192, 192,
              Bhi + (long)col0 * 192, Blo + (long)col0 * 192, 192,
              12, smu, cacc, t, wm, wn, g, tig);
    EPI_LOOP(
        uint32_t hi, lo;
        if (col0 < 384) {
            const float2 ss = *(const float2*)&d_scf[(long)row * 384 + cc];
            bsplit2(v0 * ss.x, v1 * ss.y, hi, lo);
            d_ghi[(long)row * 192 + (cc >> 1)] = hi;
            d_glo[(long)row * 192 + (cc >> 1)] = lo;
        } else if (col0 == 384) {
            const int m = cc - 384;
            const float* vp = d_v + (long)row * 384 + 3 * m;
            #pragma unroll
            for (int d = 0; d < 3; d++) {
                bsplit2(vp[d] * v0, vp[3 + d] * v1, hi, lo);
                d_vthi[(long)d * NNODES * 128 + (long)row * 128 + (m >> 1)] = hi;
                d_vtlo[(long)d * NNODES * 128 + (long)row * 128 + (m >> 1)] = lo;
            }
        } else {
            const int m = cc - 512;
            const float a0 = 1.41421356237309514547f * d_scf[(long)row * 384 + m] * v0;
            const float a1 = 1.41421356237309514547f * d_scf[(long)row * 384 + m + 1] * v1;
            const float* vp = d_v + (long)row * 384 + 3 * m;
            #pragma unroll
            for (int d = 0; d < 3; d++) {
                bsplit2(vp[d] * a0, vp[3 + d] * a1, hi, lo);
                d_vthi[(long)d * NNODES * 128 + (long)row * 128 + 64 + (m >> 1)] = hi;
                d_vtlo[(long)d * NNODES * 128 + (long)row * 128 + 64 + (m >> 1)] = lo;
            }
        }
    )
}

// GEMM3 + vGEMM merged: z=0 scalar path, z=1..3 vector component d=z-1
__global__ void __launch_bounds__(256)
gemmsv_kernel(const uint32_t* __restrict__ W0hi, const uint32_t* __restrict__ W0lo,
              const uint32_t* __restrict__ WVhi, const uint32_t* __restrict__ WVlo,
              float* __restrict__ Cs, int ldcs,
              float* __restrict__ Cv, int ldcv, int cvoff,
              float s384, float s256)
{
    GEMM_PROLOG
    const int row0 = blockIdx.y * 128, col0 = 0;
    const int z = blockIdx.z;
    if (z == 0) {
        const float scale = s384;
        bf16_loop(d_ghi + (long)row0 * 192, d_glo + (long)row0 * 192, 192,
                  W0hi, W0lo, 192, 12, smu, cacc, t, wm, wn, g, tig);
        EPI_LOOP(
            const float2 rr = *(const float2*)&d_s[(long)row * 128 + cc];
            *(float2*)&Cs[(long)row * ldcs + cc] = make_float2(v0 + rr.x, v1 + rr.y);
        )
    } else {
        const float scale = s256;
        const int d = z - 1;
        bf16_loop(d_vthi + (long)d * NNODES * 128 + (long)row0 * 128,
                  d_vtlo + (long)d * NNODES * 128 + (long)row0 * 128, 128,
                  WVhi, WVlo, 128, 8, smu, cacc, t, wm, wn, g, tig);
        EPI_LOOP(
            v0 += d_v[(long)row * 384 + 3 * cc + d];
            v1 += d_v[(long)row * 384 + 3 * (cc + 1) + d];
            Cv[(long)row * ldcv + cvoff + 3 * cc + d] = v0;
            Cv[(long)row * ldcv + cvoff + 3 * (cc + 1) + d] = v1;
        )
    }
}

// ═══════════ orchestration ═══════════
extern "C" void kernel_launch(void* const* d_in, const int* in_sizes, int n_in,
                              void* d_out, int out_size)
{
    const float* x  = (const float*)d_in[0];
    const float* w1 = (const float*)d_in[1];
    const float* w2 = (const float*)d_in[2];
    const float* w0 = (const float*)d_in[3];
    const float* wv = (const float*)d_in[4];
    const float* g0 = (const float*)d_in[5];
    const float* g1 = (const float*)d_in[6];
    float* out = (float*)d_out;

    uint32_t *w1hi, *w1lo, *w2hi, *w2lo, *w0hi, *w0lo, *wvhi, *wvlo;
    float *sb, *vb;
    cudaGetSymbolAddress((void**)&w1hi, d_w1hi); cudaGetSymbolAddress((void**)&w1lo, d_w1lo);
    cudaGetSymbolAddress((void**)&w2hi, d_w2hi); cudaGetSymbolAddress((void**)&w2lo, d_w2lo);
    cudaGetSymbolAddress((void**)&w0hi, d_w0hi); cudaGetSymbolAddress((void**)&w0lo, d_w0lo);
    cudaGetSymbolAddress((void**)&wvhi, d_wvhi); cudaGetSymbolAddress((void**)&wvlo, d_wvlo);
    cudaGetSymbolAddress((void**)&sb, d_s);
    cudaGetSymbolAddress((void**)&vb, d_v);

    cudaFuncSetAttribute((const void*)gemm1_kernel, cudaFuncAttributeMaxDynamicSharedMemorySize, SMEM_BYTES);
    cudaFuncSetAttribute((const void*)gemm2_kernel, cudaFuncAttributeMaxDynamicSharedMemorySize, SMEM_BYTES);
    cudaFuncSetAttribute((const void*)gemmsv_kernel, cudaFuncAttributeMaxDynamicSharedMemorySize, SMEM_BYTES);

    const float s384 = 1.0f / sqrtf(384.0f);
    const float s256 = 1.0f / 16.0f;

    dim3 thr(256);
    wsplit_kernel<<<dim3(480, 8), thr>>>(w1, w2, w0, wv);
    prep_kernel<<<(NNODES * 64) / 256, thr>>>(x);

    for (int layer = 0; layer < 2; layer++) {
        gemm1_kernel<<<dim3(3, 128), thr, SMEM_BYTES>>>(
            w1hi + (long)layer * 384 * 192, w1lo + (long)layer * 384 * 192, s384);
        gemm2_kernel<<<dim3(5, 128), thr, SMEM_BYTES>>>(
            w2hi + (long)layer * 640 * 192, w2lo + (long)layer * 640 * 192, s384);
        float* Cs = (layer == 0) ? sb : out;
        int ldcs = (layer == 0) ? 128 : 512;
        float* Cv = (layer == 0) ? vb : out;
        int ldcv = (layer == 0) ? 384 : 512;
        int cvoff = (layer == 0) ? 0 : 128;
        gemmsv_kernel<<<dim3(1, 128, 4), thr, SMEM_BYTES>>>(
            w0hi + (long)layer * 128 * 192, w0lo + (long)layer * 128 * 192,
            wvhi + (long)layer * 128 * 128, wvlo + (long)layer * 128 * 128,
            Cs, ldcs, Cv, ldcv, cvoff, s384, s256);
        if (layer == 0) ln_kernel<<<NNODES, 64>>>(g0, g1);
    }
}

// round 12
// speedup vs baseline: 2.3320x; 1.2690x over previous
#include <cuda_runtime.h>
#include <cuda_bf16.h>
#include <cstdint>
#include <math.h>

#define NNODES 16384

// ═══════════ scratch: packed bf16 hi/lo planes (u32 = 2 k-consecutive bf16) ═══════════
__device__ uint32_t d_schi[(long)NNODES * 192], d_sclo[(long)NNODES * 192];
__device__ uint32_t d_hhi [(long)NNODES * 192], d_hlo [(long)NNODES * 192];
__device__ uint32_t d_ghi [(long)NNODES * 192], d_glo [(long)NNODES * 192];
__device__ uint32_t d_vthi[3L * NNODES * 128],  d_vtlo[3L * NNODES * 128];
__device__ uint32_t d_w1hi[2L * 384 * 192], d_w1lo[2L * 384 * 192];
__device__ uint32_t d_w2hi[2L * 640 * 192], d_w2lo[2L * 640 * 192];
__device__ uint32_t d_w0hi[2L * 128 * 192], d_w0lo[2L * 128 * 192];
__device__ uint32_t d_wvhi[2L * 128 * 128], d_wvlo[2L * 128 * 128];
__device__ float d_scf[(long)NNODES * 384];   // fp32 sc (for gating epilogue)
__device__ float d_s  [(long)NNODES * 128];   // scalar state fp32
__device__ float d_v  [(long)NNODES * 384];   // vector state fp32 (N, C, 3)

// ═══════════ helpers ═══════════
__device__ __forceinline__ uint32_t smem_u32(const void* p) {
    uint32_t a;
    asm("{ .reg .u64 t; cvta.to.shared.u64 t, %1; cvt.u32.u64 %0, t; }" : "=r"(a) : "l"(p));
    return a;
}
__device__ __forceinline__ void cp16(uint32_t dst, const void* src) {
    asm volatile("cp.async.cg.shared.global [%0], [%1], 16;" :: "r"(dst), "l"(src));
}
__device__ __forceinline__ void bsplit2(float e0, float e1, uint32_t& hi, uint32_t& lo) {
    __nv_bfloat162 hp = __floats2bfloat162_rn(e0, e1);
    uint32_t h = *reinterpret_cast<uint32_t*>(&hp);
    float h0 = __uint_as_float(h << 16);
    float h1 = __uint_as_float(h & 0xffff0000u);
    __nv_bfloat162 lp = __floats2bfloat162_rn(e0 - h0, e1 - h1);
    hi = h;
    lo = *reinterpret_cast<uint32_t*>(&lp);
}
__device__ __forceinline__ void mma16(float* c, const uint32_t* a, const uint32_t* b) {
    asm volatile(
        "mma.sync.aligned.m16n8k16.row.col.f32.bf16.bf16.f32 "
        "{%0,%1,%2,%3},{%4,%5,%6,%7},{%8,%9},{%0,%1,%2,%3};"
        : "+f"(c[0]), "+f"(c[1]), "+f"(c[2]), "+f"(c[3])
        : "r"(a[0]), "r"(a[1]), "r"(a[2]), "r"(a[3]), "r"(b[0]), "r"(b[1]));
}
__device__ __forceinline__ void ldm4(uint32_t* r, uint32_t addr) {
    asm volatile("ldmatrix.sync.aligned.m8n8.x4.shared.b16 {%0,%1,%2,%3}, [%4];"
        : "=r"(r[0]), "=r"(r[1]), "=r"(r[2]), "=r"(r[3]) : "r"(addr));
}

// ═══════════ weight pre-split: fp32 [K][N] -> bf16 hi/lo planes [N][K/2] u32 ═══════════
__global__ void wsplit_kernel(const float* __restrict__ w1, const float* __restrict__ w2,
                              const float* __restrict__ w0, const float* __restrict__ wv)
{
    const int z = blockIdx.y, wsel = z & 3, layer = z >> 2;
    const float* W; int ldw, K2, N; uint32_t *dhi, *dlo;
    if (wsel == 0) { W = w1 + (long)layer * 384 * 384; ldw = 384; K2 = 192; N = 384;
                     dhi = d_w1hi + (long)layer * 384 * 192; dlo = d_w1lo + (long)layer * 384 * 192; }
    else if (wsel == 1) { W = w2 + (long)layer * 384 * 768; ldw = 768; K2 = 192; N = 640;
                     dhi = d_w2hi + (long)layer * 640 * 192; dlo = d_w2lo + (long)layer * 640 * 192; }
    else if (wsel == 2) { W = w0 + (long)layer * 384 * 128; ldw = 128; K2 = 192; N = 128;
                     dhi = d_w0hi + (long)layer * 128 * 192; dlo = d_w0lo + (long)layer * 128 * 192; }
    else { W = wv + (long)layer * 256 * 128; ldw = 128; K2 = 128; N = 128;
                     dhi = d_wvhi + (long)layer * 128 * 128; dlo = d_wvlo + (long)layer * 128 * 128; }
    int idx = blockIdx.x * 256 + threadIdx.x;
    if (idx >= N * K2) return;
    int n = idx / K2, k2 = idx % K2;
    float f0 = W[(long)(2 * k2) * ldw + n];
    float f1 = W[(long)(2 * k2 + 1) * ldw + n];
    uint32_t hi, lo;
    bsplit2(f0, f1, hi, lo);
    dhi[(long)n * K2 + k2] = hi;
    dlo[(long)n * K2 + k2] = lo;
}

// ═══════════ prep: x -> sc planes + scf + state ═══════════
__global__ void prep_kernel(const float* __restrict__ x)
{
    int idx = blockIdx.x * blockDim.x + threadIdx.x;
    if (idx >= NNODES * 64) return;
    int n = idx >> 6, c2 = idx & 63, c0 = 2 * c2;
    float2 s2 = *(const float2*)&x[(long)n * 512 + c0];
    const float* xv = x + (long)n * 512 + 128 + 3 * c0;
    float2 a = *(const float2*)(xv), b = *(const float2*)(xv + 2), cc = *(const float2*)(xv + 4);
    float vv0 = (a.x * a.x + a.y * a.y + b.x * b.x) * 0.57735026918962576451f;
    float vv1 = (b.y * b.y + cc.x * cc.x + cc.y * cc.y) * 0.57735026918962576451f;
    float ss0 = s2.x * s2.x, ss1 = s2.y * s2.y;
    float* scf = d_scf + (long)n * 384;
    *(float2*)&scf[c0] = s2;
    *(float2*)&scf[128 + c0] = make_float2(ss0, ss1);
    *(float2*)&scf[256 + c0] = make_float2(vv0, vv1);
    uint32_t hi, lo;
    long pb = (long)n * 192 + c2;
    bsplit2(s2.x, s2.y, hi, lo);  d_schi[pb] = hi;       d_sclo[pb] = lo;
    bsplit2(ss0, ss1, hi, lo);    d_schi[pb + 64] = hi;  d_sclo[pb + 64] = lo;
    bsplit2(vv0, vv1, hi, lo);    d_schi[pb + 128] = hi; d_sclo[pb + 128] = lo;
    *(float2*)&d_s[(long)n * 128 + c0] = s2;
    float* vb = d_v + (long)n * 384 + 3 * c0;
    *(float2*)(vb) = a; *(float2*)(vb + 2) = b; *(float2*)(vb + 4) = cc;
}

// ═══════════ equivariant layernorm (64 thr/node) fused with next prep ═══════════
__device__ __forceinline__ float red64(float v, float* sh, int t)
{
    #pragma unroll
    for (int o = 16; o; o >>= 1) v += __shfl_xor_sync(0xffffffffu, v, o);
    if ((t & 31) == 0) sh[t >> 5] = v;
    __syncthreads();
    v = sh[0] + sh[1];
    __syncthreads();
    return v;
}

__global__ void ln_kernel(const float* __restrict__ g0, const float* __restrict__ g1)
{
    __shared__ float sh[2];
    int n = blockIdx.x, t = threadIdx.x, c0 = 2 * t;
    float s0 = d_s[(long)n * 128 + c0], s1 = d_s[(long)n * 128 + c0 + 1];
    float mu = red64(s0 + s1, sh, t) * (1.0f / 128.0f);
    float dd0 = s0 - mu, dd1 = s1 - mu;
    float var = red64(dd0 * dd0 + dd1 * dd1, sh, t) * (1.0f / 128.0f);
    float sd = sqrtf(var + 1e-6f);
    float* vp = d_v + (long)n * 384 + 3 * c0;
    float v0 = vp[0], v1 = vp[1], v2 = vp[2], v3 = vp[3], v4 = vp[4], v5 = vp[5];
    float msq = red64(v0*v0 + v1*v1 + v2*v2 + v3*v3 + v4*v4 + v5*v5, sh, t) * (1.0f / 384.0f);
    float rms = sqrtf(msq + 1e-6f);
    float sn0 = dd0 / sd * g0[c0], sn1 = dd1 / sd * g0[c0 + 1];
    d_s[(long)n * 128 + c0] = sn0; d_s[(long)n * 128 + c0 + 1] = sn1;
    float sc0 = g1[c0] / rms, sc1 = g1[c0 + 1] / rms;
    float nx0 = v0 * sc0, ny0 = v1 * sc0, nz0 = v2 * sc0;
    float nx1 = v3 * sc1, ny1 = v4 * sc1, nz1 = v5 * sc1;
    vp[0] = nx0; vp[1] = ny0; vp[2] = nz0; vp[3] = nx1; vp[4] = ny1; vp[5] = nz1;
    float vv0 = (nx0*nx0 + ny0*ny0 + nz0*nz0) * 0.57735026918962576451f;
    float vv1 = (nx1*nx1 + ny1*ny1 + nz1*nz1) * 0.57735026918962576451f;
    float* scf = d_scf + (long)n * 384;
    scf[c0] = sn0; scf[c0 + 1] = sn1;
    scf[128 + c0] = sn0 * sn0; scf[128 + c0 + 1] = sn1 * sn1;
    scf[256 + c0] = vv0; scf[256 + c0 + 1] = vv1;
    uint32_t hi, lo;
    long pb = (long)n * 192 + t;
    bsplit2(sn0, sn1, hi, lo);          d_schi[pb] = hi;       d_sclo[pb] = lo;
    bsplit2(sn0*sn0, sn1*sn1, hi, lo);  d_schi[pb + 64] = hi;  d_sclo[pb + 64] = lo;
    bsplit2(vv0, vv1, hi, lo);          d_schi[pb + 128] = hi; d_sclo[pb + 128] = lo;
}

// ═══════════ pure-bf16 mainloop (ldmatrix fragments) ═══════════
// SMEM per stage (u32): Ahi[128][20] | Alo | Bhi | Blo ; 16 data u32 + 4 pad per row.
static constexpr int ST = 20;
static constexpr int OFF_ALO = 128 * ST;
static constexpr int OFF_BHI = 2 * 128 * ST;
static constexpr int OFF_BLO = 3 * 128 * ST;
static constexpr int STAGE32 = 4 * 128 * ST;
static constexpr uint32_t SMEM_BYTES = 2 * STAGE32 * 4;   // 81920

__device__ __forceinline__ void bf16_loop(
    const uint32_t* __restrict__ Ahi, const uint32_t* __restrict__ Alo, int lda32,
    const uint32_t* __restrict__ Bhi, const uint32_t* __restrict__ Blo, int ldb32,
    int nch, uint32_t* sm, float (*cacc)[4],
    int t, int wm, int wn)
{
    const uint32_t smb = smem_u32(sm);
    const int lane = t & 31;
    // ldmatrix per-lane offsets (u32 units within a stage)
    const int la = lane & 15, ha = lane >> 4;                       // A: row within tile, k-half
    const int lb = lane & 7, tb = (lane >> 4) & 1, hb = (lane >> 3) & 1;  // B
    const uint32_t aoff0 = (uint32_t)((wm + la) * ST + ha * 4);
    const uint32_t boff0 = (uint32_t)((wn + tb * 8 + lb) * ST + hb * 4);

    {
        const uint32_t s0 = smb;
        #pragma unroll
        for (int i = 0; i < 2; i++) {
            int idx = t + i * 256;
            int r = idx >> 2, c4 = (idx & 3) * 4;
            cp16(s0 + (uint32_t)(r * ST + c4) * 4u,           Ahi + (long)r * lda32 + c4);
            cp16(s0 + (uint32_t)(OFF_ALO + r * ST + c4) * 4u, Alo + (long)r * lda32 + c4);
            cp16(s0 + (uint32_t)(OFF_BHI + r * ST + c4) * 4u, Bhi + (long)r * ldb32 + c4);
            cp16(s0 + (uint32_t)(OFF_BLO + r * ST + c4) * 4u, Blo + (long)r * ldb32 + c4);
        }
        asm volatile("cp.async.commit_group;" ::: "memory");
    }
    for (int ch = 0; ch < nch; ch++) {
        const bool more = (ch + 1 < nch);
        if (more) {
            const int kt = (ch + 1) * 16;
            const uint32_t s0 = smb + (uint32_t)(((ch + 1) & 1) * STAGE32) * 4u;
            #pragma unroll
            for (int i = 0; i < 2; i++) {
                int idx = t + i * 256;
                int r = idx >> 2, c4 = (idx & 3) * 4;
                cp16(s0 + (uint32_t)(r * ST + c4) * 4u,           Ahi + (long)r * lda32 + kt + c4);
                cp16(s0 + (uint32_t)(OFF_ALO + r * ST + c4) * 4u, Alo + (long)r * lda32 + kt + c4);
                cp16(s0 + (uint32_t)(OFF_BHI + r * ST + c4) * 4u, Bhi + (long)r * ldb32 + kt + c4);
                cp16(s0 + (uint32_t)(OFF_BLO + r * ST + c4) * 4u, Blo + (long)r * ldb32 + kt + c4);
            }
            asm volatile("cp.async.commit_group;" ::: "memory");
            asm volatile("cp.async.wait_group 1;" ::: "memory");
        } else {
            asm volatile("cp.async.wait_group 0;" ::: "memory");
        }
        __syncthreads();
        const uint32_t sbase = smb + (uint32_t)((ch & 1) * STAGE32) * 4u;
        #pragma unroll
        for (int ks = 0; ks < 2; ks++) {
            const uint32_t ko = (uint32_t)(ks * 8);
            uint32_t ah[4][4], al[4][4];
            #pragma unroll
            for (int mt = 0; mt < 4; mt++) {
                ldm4(ah[mt], sbase + (aoff0 + (uint32_t)(mt * 16 * ST) + ko) * 4u);
                ldm4(al[mt], sbase + (OFF_ALO + aoff0 + (uint32_t)(mt * 16 * ST) + ko) * 4u);
            }
            uint32_t bh[2][4], bl[2][4];   // pair p: r0,r1 = tile 2p ; r2,r3 = tile 2p+1
            #pragma unroll
            for (int p = 0; p < 2; p++) {
                ldm4(bh[p], sbase + (OFF_BHI + boff0 + (uint32_t)(p * 16 * ST) + ko) * 4u);
                ldm4(bl[p], sbase + (OFF_BLO + boff0 + (uint32_t)(p * 16 * ST) + ko) * 4u);
            }
            #pragma unroll
            for (int mt = 0; mt < 4; mt++)
                #pragma unroll
                for (int nt = 0; nt < 4; nt++) {
                    const uint32_t* bhr = &bh[nt >> 1][(nt & 1) * 2];
                    const uint32_t* blr = &bl[nt >> 1][(nt & 1) * 2];
                    mma16(cacc[mt * 4 + nt], ah[mt], bhr);
                    mma16(cacc[mt * 4 + nt], al[mt], bhr);
                    mma16(cacc[mt * 4 + nt], ah[mt], blr);
                }
        }
        if (more) __syncthreads();
    }
}

#define GEMM_PROLOG \
    extern __shared__ uint32_t smu[]; \
    const int t = threadIdx.x, lane = t & 31, w = t >> 5; \
    const int g = lane >> 2, tig = lane & 3; \
    const int wm = (w & 1) * 64, wn = (w >> 1) * 32; \
    float cacc[16][4]; \
    _Pragma("unroll") \
    for (int i = 0; i < 16; i++) { cacc[i][0] = cacc[i][1] = cacc[i][2] = cacc[i][3] = 0.0f; }

#define EPI_LOOP(...) \
    _Pragma("unroll") \
    for (int mt = 0; mt < 4; mt++) \
        _Pragma("unroll") \
        for (int nt = 0; nt < 4; nt++) { \
            const float* cf = cacc[mt * 4 + nt]; \
            const int rb = row0 + wm + mt * 16 + g; \
            const int cc = col0 + wn + nt * 8 + 2 * tig; \
            _Pragma("unroll") \
            for (int hh = 0; hh < 2; hh++) { \
                const int row = rb + hh * 8; \
                float v0 = cf[hh * 2 + 0] * scale; \
                float v1 = cf[hh * 2 + 1] * scale; \
                __VA_ARGS__ \
            } \
        }

// GEMM1: h = silu(sc @ W1 / sqrt384) -> h planes
__global__ void __launch_bounds__(256, 2)
gemm1_kernel(const uint32_t* __restrict__ Bhi, const uint32_t* __restrict__ Blo, float scale)
{
    GEMM_PROLOG
    const int row0 = blockIdx.y * 128, col0 = blockIdx.x * 128;
    bf16_loop(d_schi + (long)row0 * 192, d_sclo + (long)row0 * 192, 192,
              Bhi + (long)col0 * 192, Blo + (long)col0 * 192, 192,
              12, smu, cacc, t, wm, wn);
    EPI_LOOP(
        v0 = v0 / (1.0f + expf(-v0));
        v1 = v1 / (1.0f + expf(-v1));
        uint32_t hi, lo;
        bsplit2(v0, v1, hi, lo);
        d_hhi[(long)row * 192 + (cc >> 1)] = hi;
        d_hlo[(long)row * 192 + (cc >> 1)] = lo;
    )
}

// GEMM2: g = h @ W2[:, :640] / sqrt384, fused gating -> g planes + vt planes
__global__ void __launch_bounds__(256, 2)
gemm2_kernel(const uint32_t* __restrict__ Bhi, const uint32_t* __restrict__ Blo, float scale)
{
    GEMM_PROLOG
    const int row0 = blockIdx.y * 128, col0 = blockIdx.x * 128;
    bf16_loop(d_hhi + (long)row0 * 192, d_hlo + (long)row0 * 192, 192,
              Bhi + (long)col0 * 192, Blo + (long)col0 * 192, 192,
              12, smu, cacc, t, wm, wn);
    EPI_LOOP(
        uint32_t hi, lo;
        if (col0 < 384) {
            const float2 ss = *(const float2*)&d_scf[(long)row * 384 + cc];
            bsplit2(v0 * ss.x, v1 * ss.y, hi, lo);
            d_ghi[(long)row * 192 + (cc >> 1)] = hi;
            d_glo[(long)row * 192 + (cc >> 1)] = lo;
        } else if (col0 == 384) {
            const int m = cc - 384;
            const float* vp = d_v + (long)row * 384 + 3 * m;
            #pragma unroll
            for (int d = 0; d < 3; d++) {
                bsplit2(vp[d] * v0, vp[3 + d] * v1, hi, lo);
                d_vthi[(long)d * NNODES * 128 + (long)row * 128 + (m >> 1)] = hi;
                d_vtlo[(long)d * NNODES * 128 + (long)row * 128 + (m >> 1)] = lo;
            }
        } else {
            const int m = cc - 512;
            const float a0 = 1.41421356237309514547f * d_scf[(long)row * 384 + m] * v0;
            const float a1 = 1.41421356237309514547f * d_scf[(long)row * 384 + m + 1] * v1;
            const float* vp = d_v + (long)row * 384 + 3 * m;
            #pragma unroll
            for (int d = 0; d < 3; d++) {
                bsplit2(vp[d] * a0, vp[3 + d] * a1, hi, lo);
                d_vthi[(long)d * NNODES * 128 + (long)row * 128 + 64 + (m >> 1)] = hi;
                d_vtlo[(long)d * NNODES * 128 + (long)row * 128 + 64 + (m >> 1)] = lo;
            }
        }
    )
}

// GEMM3 + vGEMM merged: z=0 scalar path, z=1..3 vector component d=z-1
__global__ void __launch_bounds__(256, 2)
gemmsv_kernel(const uint32_t* __restrict__ W0hi, const uint32_t* __restrict__ W0lo,
              const uint32_t* __restrict__ WVhi, const uint32_t* __restrict__ WVlo,
              float* __restrict__ Cs, int ldcs,
              float* __restrict__ Cv, int ldcv, int cvoff,
              float s384, float s256)
{
    GEMM_PROLOG
    const int row0 = blockIdx.y * 128, col0 = 0;
    const int z = blockIdx.z;
    if (z == 0) {
        const float scale = s384;
        bf16_loop(d_ghi + (long)row0 * 192, d_glo + (long)row0 * 192, 192,
                  W0hi, W0lo, 192, 12, smu, cacc, t, wm, wn);
        EPI_LOOP(
            const float2 rr = *(const float2*)&d_s[(long)row * 128 + cc];
            *(float2*)&Cs[(long)row * ldcs + cc] = make_float2(v0 + rr.x, v1 + rr.y);
        )
    } else {
        const float scale = s256;
        const int d = z - 1;
        bf16_loop(d_vthi + (long)d * NNODES * 128 + (long)row0 * 128,
                  d_vtlo + (long)d * NNODES * 128 + (long)row0 * 128, 128,
                  WVhi, WVlo, 128, 8, smu, cacc, t, wm, wn);
        EPI_LOOP(
            v0 += d_v[(long)row * 384 + 3 * cc + d];
            v1 += d_v[(long)row * 384 + 3 * (cc + 1) + d];
            Cv[(long)row * ldcv + cvoff + 3 * cc + d] = v0;
            Cv[(long)row * ldcv + cvoff + 3 * (cc + 1) + d] = v1;
        )
    }
}

// ═══════════ orchestration ═══════════
extern "C" void kernel_launch(void* const* d_in, const int* in_sizes, int n_in,
                              void* d_out, int out_size)
{
    const float* x  = (const float*)d_in[0];
    const float* w1 = (const float*)d_in[1];
    const float* w2 = (const float*)d_in[2];
    const float* w0 = (const float*)d_in[3];
    const float* wv = (const float*)d_in[4];
    const float* g0 = (const float*)d_in[5];
    const float* g1 = (const float*)d_in[6];
    float* out = (float*)d_out;

    uint32_t *w1hi, *w1lo, *w2hi, *w2lo, *w0hi, *w0lo, *wvhi, *wvlo;
    float *sb, *vb;
    cudaGetSymbolAddress((void**)&w1hi, d_w1hi); cudaGetSymbolAddress((void**)&w1lo, d_w1lo);
    cudaGetSymbolAddress((void**)&w2hi, d_w2hi); cudaGetSymbolAddress((void**)&w2lo, d_w2lo);
    cudaGetSymbolAddress((void**)&w0hi, d_w0hi); cudaGetSymbolAddress((void**)&w0lo, d_w0lo);
    cudaGetSymbolAddress((void**)&wvhi, d_wvhi); cudaGetSymbolAddress((void**)&wvlo, d_wvlo);
    cudaGetSymbolAddress((void**)&sb, d_s);
    cudaGetSymbolAddress((void**)&vb, d_v);

    cudaFuncSetAttribute((const void*)gemm1_kernel, cudaFuncAttributeMaxDynamicSharedMemorySize, SMEM_BYTES);
    cudaFuncSetAttribute((const void*)gemm2_kernel, cudaFuncAttributeMaxDynamicSharedMemorySize, SMEM_BYTES);
    cudaFuncSetAttribute((const void*)gemmsv_kernel, cudaFuncAttributeMaxDynamicSharedMemorySize, SMEM_BYTES);

    const float s384 = 1.0f / sqrtf(384.0f);
    const float s256 = 1.0f / 16.0f;

    dim3 thr(256);
    wsplit_kernel<<<dim3(480, 8), thr>>>(w1, w2, w0, wv);
    prep_kernel<<<(NNODES * 64) / 256, thr>>>(x);

    for (int layer = 0; layer < 2; layer++) {
        gemm1_kernel<<<dim3(3, 128), thr, SMEM_BYTES>>>(
            w1hi + (long)layer * 384 * 192, w1lo + (long)layer * 384 * 192, s384);
        gemm2_kernel<<<dim3(5, 128), thr, SMEM_BYTES>>>(
            w2hi + (long)layer * 640 * 192, w2lo + (long)layer * 640 * 192, s384);
        float* Cs = (layer == 0) ? sb : out;
        int ldcs = (layer == 0) ? 128 : 512;
        float* Cv = (layer == 0) ? vb : out;
        int ldcv = (layer == 0) ? 384 : 512;
        int cvoff = (layer == 0) ? 0 : 128;
        gemmsv_kernel<<<dim3(1, 128, 4), thr, SMEM_BYTES>>>(
            w0hi + (long)layer * 128 * 192, w0lo + (long)layer * 128 * 192,
            wvhi + (long)layer * 128 * 128, wvlo + (long)layer * 128 * 128,
            Cs, ldcs, Cv, ldcv, cvoff, s384, s256);
        if (layer == 0) ln_kernel<<<NNODES, 64>>>(g0, g1);
    }
}